// round 17
// baseline (speedup 1.0000x reference)
#include <cuda_runtime.h>

// BatchNorm over features: X[N, D], stats over axis 0. N=131072, D=512, fp32.
//
// Round 17: resubmission of Round 16 (infra failure, never measured).
// R14 theory with the sm_103a-legal encoding: evict_last demands 32-byte
// loads (ld.global.L2::evict_last.v4.b64). Phase-1 tail (last 192 rows per
// block, ~113.6MB chip-wide ~= L2 capacity) is loaded 32B/thread in a
// remapped layout with its own accumulators + reduction into g_psum2/g_psq2;
// finalize sums both partial sets. Phase 2 (back-to-front LIFO) harvests the
// protected tail first. Y stores remain __stcs (best measured).

#define NROWS  131072
#define DCOLS  512
#define DV     128                  // DCOLS/4 float4 quads per row
#define GRID   296                  // 2 blocks/SM x 148 SMs
#define NTH    512
#define NCH16  (NROWS / 16)         // 8192 16-row chunks
#define TAILR  192                  // evict-last rows per block (384KB/blk)

// Scratch (__device__ globals; allocation forbidden).
__device__ float g_psum [DCOLS * GRID];   // main-mapping partials
__device__ float g_psq  [DCOLS * GRID];
__device__ float g_psum2[DCOLS * GRID];   // tail-mapping partials
__device__ float g_psq2 [DCOLS * GRID];
__device__ __align__(16) float g_scale[DCOLS];
__device__ __align__(16) float g_shift[DCOLS];
__device__ unsigned g_bar0;
__device__ unsigned g_bar1;

__global__ void bn_init_kernel() { g_bar0 = 0u; g_bar1 = 0u; }

// Grid-wide barrier; safe because all GRID blocks are co-resident (occ 2).
__device__ __forceinline__ void grid_barrier(unsigned* ctr, int tid) {
    __syncthreads();
    if (tid == 0) {
        __threadfence();
        atomicAdd(ctr, 1u);
        unsigned v;
        do {
            asm volatile("ld.acquire.gpu.u32 %0, [%1];"
                         : "=r"(v) : "l"(ctr) : "memory");
            if (v >= GRID) break;
            __nanosleep(64);
        } while (true);
    }
    __syncthreads();
}

// 32-byte evict-last load (the only width ptxas accepts on sm_103a).
__device__ __forceinline__ void ld_el32(const float4* p, float4& a, float4& b) {
    unsigned long long r0, r1, r2, r3;
    asm volatile("ld.global.L2::evict_last.v4.b64 {%0, %1, %2, %3}, [%4];"
                 : "=l"(r0), "=l"(r1), "=l"(r2), "=l"(r3) : "l"(p));
    a.x = __uint_as_float((unsigned)r0); a.y = __uint_as_float((unsigned)(r0 >> 32));
    a.z = __uint_as_float((unsigned)r1); a.w = __uint_as_float((unsigned)(r1 >> 32));
    b.x = __uint_as_float((unsigned)r2); b.y = __uint_as_float((unsigned)(r2 >> 32));
    b.z = __uint_as_float((unsigned)r3); b.w = __uint_as_float((unsigned)(r3 >> 32));
}

__device__ __forceinline__ void acc4(const float4& x, float4& s, float4& q) {
    s.x += x.x; s.y += x.y; s.z += x.z; s.w += x.w;
    q.x = fmaf(x.x, x.x, q.x); q.y = fmaf(x.y, x.y, q.y);
    q.z = fmaf(x.z, x.z, q.z); q.w = fmaf(x.w, x.w, q.w);
}

__global__ __launch_bounds__(NTH, 2)
void bn_fused_kernel(const float4* __restrict__ Xv, float4* __restrict__ Yv,
                     const float* __restrict__ gamma,
                     const float* __restrict__ beta) {
    __shared__ float4 shs[NTH];
    __shared__ float4 shq[NTH];

    const int b   = blockIdx.x;
    const int tid = threadIdx.x;
    const int cq  = tid & 127;   // main mapping: column quad 0..127
    const int lr  = tid >> 7;    //               row lane    0..3

    // Contiguous region: chunks [cs, ce) of 16 rows (27 or 28 chunks).
    const int cs = (int)(((long long)b       * NCH16) / GRID);
    const int ce = (int)(((long long)(b + 1) * NCH16) / GRID);
    const int R     = (ce - cs) * 16;          // rows in region (432 or 448)
    const int F     = R - TAILR;               // front rows (240 or 256)
    const int nIter = R / 4;                   // phase-2 steps per thread
    const size_t rowbase = (size_t)cs * 16;
    const size_t base = (rowbase + (size_t)lr) * DV + (size_t)cq;

    // ---------------- Phase 1a: front rows, main mapping ----------------
    float4 ms = make_float4(0.f, 0.f, 0.f, 0.f);
    float4 mq = make_float4(0.f, 0.f, 0.f, 0.f);

    for (int i = 0; i < F / 4; i += 4) {
        float4 x0 = Xv[base + (size_t)(i + 0) * (4 * DV)];
        float4 x1 = Xv[base + (size_t)(i + 1) * (4 * DV)];
        float4 x2 = Xv[base + (size_t)(i + 2) * (4 * DV)];
        float4 x3 = Xv[base + (size_t)(i + 3) * (4 * DV)];
        acc4(x0, ms, mq); acc4(x1, ms, mq);
        acc4(x2, ms, mq); acc4(x3, ms, mq);
    }

    // ---------------- Phase 1b: tail rows, 32B evict-last mapping ----------
    // 512 threads = 64 segments (32B = 2 quads) x 8 row lanes.
    const int sg  = tid & 63;    // 32B segment 0..63
    const int lr8 = tid >> 6;    // row lane 0..7
    float4 tsA = make_float4(0.f, 0.f, 0.f, 0.f);
    float4 tqA = make_float4(0.f, 0.f, 0.f, 0.f);
    float4 tsB = make_float4(0.f, 0.f, 0.f, 0.f);
    float4 tqB = make_float4(0.f, 0.f, 0.f, 0.f);
    {
        const size_t tbase = (rowbase + (size_t)F + (size_t)lr8) * DV
                           + (size_t)(sg * 2);
        for (int j = 0; j < TAILR / 8; j += 2) {
            float4 a0, b0, a1, b1;
            ld_el32(&Xv[tbase + (size_t)(j + 0) * (8 * DV)], a0, b0);
            ld_el32(&Xv[tbase + (size_t)(j + 1) * (8 * DV)], a1, b1);
            acc4(a0, tsA, tqA); acc4(b0, tsB, tqB);
            acc4(a1, tsA, tqA); acc4(b1, tsB, tqB);
        }
    }

    // ---------------- Reduce main partials ----------------
    shs[tid] = ms; shq[tid] = mq;
    __syncthreads();
    if (lr == 0) {
        float4 s = shs[cq];
        float4 q = shq[cq];
        #pragma unroll
        for (int k = 1; k < 4; k++) {
            float4 a  = shs[cq + 128 * k];
            float4 c2 = shq[cq + 128 * k];
            s.x += a.x; s.y += a.y; s.z += a.z; s.w += a.w;
            q.x += c2.x; q.y += c2.y; q.z += c2.z; q.w += c2.w;
        }
        const int c0 = 4 * cq;
        g_psum[(size_t)(c0 + 0) * GRID + b] = s.x;
        g_psum[(size_t)(c0 + 1) * GRID + b] = s.y;
        g_psum[(size_t)(c0 + 2) * GRID + b] = s.z;
        g_psum[(size_t)(c0 + 3) * GRID + b] = s.w;
        g_psq [(size_t)(c0 + 0) * GRID + b] = q.x;
        g_psq [(size_t)(c0 + 1) * GRID + b] = q.y;
        g_psq [(size_t)(c0 + 2) * GRID + b] = q.z;
        g_psq [(size_t)(c0 + 3) * GRID + b] = q.w;
    }
    __syncthreads();

    // ---------------- Reduce tail partials (two passes: quads 2sg, 2sg+1) --
    shs[tid] = tsA; shq[tid] = tqA;
    __syncthreads();
    if (tid < 64) {
        float4 s = shs[tid];
        float4 q = shq[tid];
        #pragma unroll
        for (int k = 1; k < 8; k++) {
            float4 a  = shs[tid + 64 * k];
            float4 c2 = shq[tid + 64 * k];
            s.x += a.x; s.y += a.y; s.z += a.z; s.w += a.w;
            q.x += c2.x; q.y += c2.y; q.z += c2.z; q.w += c2.w;
        }
        const int c0 = 8 * tid;          // quad 2*sg -> columns 8sg..8sg+3
        g_psum2[(size_t)(c0 + 0) * GRID + b] = s.x;
        g_psum2[(size_t)(c0 + 1) * GRID + b] = s.y;
        g_psum2[(size_t)(c0 + 2) * GRID + b] = s.z;
        g_psum2[(size_t)(c0 + 3) * GRID + b] = s.w;
        g_psq2 [(size_t)(c0 + 0) * GRID + b] = q.x;
        g_psq2 [(size_t)(c0 + 1) * GRID + b] = q.y;
        g_psq2 [(size_t)(c0 + 2) * GRID + b] = q.z;
        g_psq2 [(size_t)(c0 + 3) * GRID + b] = q.w;
    }
    __syncthreads();
    shs[tid] = tsB; shq[tid] = tqB;
    __syncthreads();
    if (tid < 64) {
        float4 s = shs[tid];
        float4 q = shq[tid];
        #pragma unroll
        for (int k = 1; k < 8; k++) {
            float4 a  = shs[tid + 64 * k];
            float4 c2 = shq[tid + 64 * k];
            s.x += a.x; s.y += a.y; s.z += a.z; s.w += a.w;
            q.x += c2.x; q.y += c2.y; q.z += c2.z; q.w += c2.w;
        }
        const int c0 = 8 * tid + 4;      // quad 2*sg+1 -> columns 8sg+4..8sg+7
        g_psum2[(size_t)(c0 + 0) * GRID + b] = s.x;
        g_psum2[(size_t)(c0 + 1) * GRID + b] = s.y;
        g_psum2[(size_t)(c0 + 2) * GRID + b] = s.z;
        g_psum2[(size_t)(c0 + 3) * GRID + b] = s.w;
        g_psq2 [(size_t)(c0 + 0) * GRID + b] = q.x;
        g_psq2 [(size_t)(c0 + 1) * GRID + b] = q.y;
        g_psq2 [(size_t)(c0 + 2) * GRID + b] = q.z;
        g_psq2 [(size_t)(c0 + 3) * GRID + b] = q.w;
    }

    // ---------------- Barrier 1: all partials visible ----------------
    grid_barrier(&g_bar0, tid);

    // ---------------- Finalize: block b handles columns b, b+GRID ----------
    {
        __shared__ float ss[16];
        __shared__ float sq[16];
        for (int c = b; c < DCOLS; c += GRID) {
            float s = 0.f, q = 0.f;
            if (tid < GRID) {
                s = g_psum [(size_t)c * GRID + tid]
                  + g_psum2[(size_t)c * GRID + tid];
                q = g_psq  [(size_t)c * GRID + tid]
                  + g_psq2 [(size_t)c * GRID + tid];
            }
            #pragma unroll
            for (int off = 16; off > 0; off >>= 1) {
                s += __shfl_down_sync(0xFFFFFFFFu, s, off);
                q += __shfl_down_sync(0xFFFFFFFFu, q, off);
            }
            const int warp = tid >> 5;
            const int lane = tid & 31;
            if (lane == 0) { ss[warp] = s; sq[warp] = q; }
            __syncthreads();
            if (tid < 16) {
                s = ss[tid];
                q = sq[tid];
                #pragma unroll
                for (int off = 8; off > 0; off >>= 1) {
                    s += __shfl_down_sync(0x0000FFFFu, s, off);
                    q += __shfl_down_sync(0x0000FFFFu, q, off);
                }
                if (tid == 0) {
                    const float inv_n = 1.0f / (float)NROWS;
                    float mean = s * inv_n;
                    float var  = fmaf(-mean, mean, q * inv_n);
                    float inv  = rsqrtf(var);       // no epsilon (matches reference)
                    float scv  = inv * gamma[c];
                    g_scale[c] = scv;
                    g_shift[c] = fmaf(-mean, scv, beta[c]);
                }
            }
            __syncthreads();
        }
    }

    // ---------------- Barrier 2: scale/shift visible ----------------
    grid_barrier(&g_bar1, tid);

    const float4 sc = reinterpret_cast<const float4*>(g_scale)[cq];
    const float4 sh = reinterpret_cast<const float4*>(g_shift)[cq];

    // ---------------- Phase 2: normalize BACK-TO-FRONT ----------------
    // Evict-last tail hits first (protected class), then DRAM for the rest.
    for (int j = nIter - 4; j >= 0; j -= 4) {
        const size_t i0 = base + (size_t)(j + 0) * (4 * DV);
        const size_t i1 = base + (size_t)(j + 1) * (4 * DV);
        const size_t i2 = base + (size_t)(j + 2) * (4 * DV);
        const size_t i3 = base + (size_t)(j + 3) * (4 * DV);
        float4 x0 = Xv[i0];
        float4 x1 = Xv[i1];
        float4 x2 = Xv[i2];
        float4 x3 = Xv[i3];
        float4 y;
        y.x = fmaf(x3.x, sc.x, sh.x); y.y = fmaf(x3.y, sc.y, sh.y);
        y.z = fmaf(x3.z, sc.z, sh.z); y.w = fmaf(x3.w, sc.w, sh.w);
        __stcs(&Yv[i3], y);
        y.x = fmaf(x2.x, sc.x, sh.x); y.y = fmaf(x2.y, sc.y, sh.y);
        y.z = fmaf(x2.z, sc.z, sh.z); y.w = fmaf(x2.w, sc.w, sh.w);
        __stcs(&Yv[i2], y);
        y.x = fmaf(x1.x, sc.x, sh.x); y.y = fmaf(x1.y, sc.y, sh.y);
        y.z = fmaf(x1.z, sc.z, sh.z); y.w = fmaf(x1.w, sc.w, sh.w);
        __stcs(&Yv[i1], y);
        y.x = fmaf(x0.x, sc.x, sh.x); y.y = fmaf(x0.y, sc.y, sh.y);
        y.z = fmaf(x0.z, sc.z, sh.z); y.w = fmaf(x0.w, sc.w, sh.w);
        __stcs(&Yv[i0], y);
    }
}

// ---------------------------------------------------------------------------
extern "C" void kernel_launch(void* const* d_in, const int* in_sizes, int n_in,
                              void* d_out, int out_size) {
    const float* X     = (const float*)d_in[0];
    const float* gamma = (const float*)d_in[1];
    const float* beta  = (const float*)d_in[2];
    float*       Y     = (float*)d_out;

    bn_init_kernel<<<1, 1>>>();
    bn_fused_kernel<<<GRID, NTH>>>((const float4*)X, (float4*)Y, gamma, beta);
}